// round 16
// baseline (speedup 1.0000x reference)
#include <cuda_runtime.h>
#include <cstdint>

#define NB   32    // num 4x4 blocks
#define BS   4
#define DIM  128   // NB*BS
#define NREL 16    // edge relations (blocks[16] = self-loop)

// ---------------------------------------------------------------------------
// Self-loop kernel: grid-stride, warp-per-node, lane b = block b.
// W (relation 16) register-resident, loaded once per warp.
// Also initializes d_out (poisoned). mask is bool serialized as int32.
// ---------------------------------------------------------------------------
__global__ __launch_bounds__(256) void self_kernel(
    const float* __restrict__ x,
    const int*   __restrict__ mask,
    const float* __restrict__ blocks,
    float* __restrict__ out,
    int n_nodes)
{
    const int lane = threadIdx.x & 31;
    const int warp = (blockIdx.x * blockDim.x + threadIdx.x) >> 5;
    const int nw   = (gridDim.x * blockDim.x) >> 5;

    const float4* Wp = (const float4*)blocks + ((size_t)NREL * NB + lane) * 4;
    const float4 w0 = __ldg(Wp + 0);
    const float4 w1 = __ldg(Wp + 1);
    const float4 w2 = __ldg(Wp + 2);
    const float4 w3 = __ldg(Wp + 3);

    for (int n = warp; n < n_nodes; n += nw) {
        float4 o = make_float4(0.f, 0.f, 0.f, 0.f);
        if (__ldg(mask + n) != 0) {
            float4 xi = __ldg((const float4*)(x + (size_t)n * DIM) + lane);
            o.x = xi.x * w0.x + xi.y * w1.x + xi.z * w2.x + xi.w * w3.x;
            o.y = xi.x * w0.y + xi.y * w1.y + xi.z * w2.y + xi.w * w3.y;
            o.z = xi.x * w0.z + xi.y * w1.z + xi.z * w2.z + xi.w * w3.z;
            o.w = xi.x * w0.w + xi.y * w1.w + xi.z * w2.w + xi.w * w3.w;
        }
        *((float4*)(out + (size_t)n * DIM) + lane) = o;
    }
}

// ---------------------------------------------------------------------------
// Edge kernel: relation-specialized CTAs (blockIdx.y = relation g),
// register-resident W (loaded once per warp lifetime). Warps scan 32-edge
// chunks: coalesced et load, ballot et==g, matched lanes pack s|(t<<16),
// SERIAL ffs loop (lowest ALU overhead — proven fastest structure):
//   2 shfls -> coalesced x[src] gather (LDG.128) -> 4x4 GEMV -> red.v4.
// Grid sized for 6 CTAs/SM residency (regs=40).
// ---------------------------------------------------------------------------
#define EDGE_THREADS 256
#define EDGE_G       74    // 74*16 = 1184 CTAs (6/SM resident at 40 regs)

__global__ __launch_bounds__(EDGE_THREADS) void edge_kernel(
    const float* __restrict__ x,
    const int*   __restrict__ src,
    const int*   __restrict__ tgt,
    const int*   __restrict__ et,
    const float* __restrict__ ew,
    const float* __restrict__ blocks,
    float* __restrict__ out,
    int n_edges)
{
    const int g    = blockIdx.y;
    const int lane = threadIdx.x & 31;

    // Register-resident W for relation g, block = lane
    const float4* Wp = (const float4*)blocks + ((size_t)g * NB + lane) * 4;
    const float4 w0 = __ldg(Wp + 0);
    const float4 w1 = __ldg(Wp + 1);
    const float4 w2 = __ldg(Wp + 2);
    const float4 w3 = __ldg(Wp + 3);

    const int warp = (blockIdx.x * EDGE_THREADS + threadIdx.x) >> 5;
    const int nw   = (gridDim.x * EDGE_THREADS) >> 5;
    const int E2   = 2 * n_edges;
    const int nch  = (E2 + 31) >> 5;

    for (int c = warp; c < nch; c += nw) {
        const int d     = (c << 5) + lane;
        const bool valid = (d < E2);
        const bool fwd   = (d < n_edges);
        const int  e     = fwd ? d : d - n_edges;

        int r = -1;
        if (valid) r = __ldg(et + e);

        unsigned m = __ballot_sync(0xffffffffu, r == g);
        if (m == 0u) continue;

        // matching lanes fetch packed metadata: s | (t<<16)
        int   st_l = 0;
        float w_l  = 0.f;
        if (r == g) {
            int s = __ldg(fwd ? src + e : tgt + e);
            int t = __ldg(fwd ? tgt + e : src + e);
            st_l = s | (t << 16);
            w_l  = __ldg(ew + e);
        }

        while (m) {
            const int k = __ffs(m) - 1;
            m &= m - 1;

            const int   st = __shfl_sync(0xffffffffu, st_l, k);
            const float w  = __shfl_sync(0xffffffffu, w_l,  k);
            const int s = st & 0xFFFF;
            const int t = st >> 16;

            float4 xi = __ldg((const float4*)(x + (size_t)s * DIM) + lane);

            float4 o;
            o.x = (xi.x * w0.x + xi.y * w1.x + xi.z * w2.x + xi.w * w3.x) * w;
            o.y = (xi.x * w0.y + xi.y * w1.y + xi.z * w2.y + xi.w * w3.y) * w;
            o.z = (xi.x * w0.z + xi.y * w1.z + xi.z * w2.z + xi.w * w3.z) * w;
            o.w = (xi.x * w0.w + xi.y * w1.w + xi.z * w2.w + xi.w * w3.w) * w;

            float* dst = out + (size_t)t * DIM + lane * 4;   // 16B aligned
            asm volatile("red.global.add.v4.f32 [%0], {%1, %2, %3, %4};"
                         :: "l"(dst), "f"(o.x), "f"(o.y), "f"(o.z), "f"(o.w));
        }
    }
}

// ---------------------------------------------------------------------------
// Inputs (metadata order):
//   0: x              float32 (10000*128)
//   1: node_keep_mask int32   (10000)
//   2: source         int32   (160000)
//   3: target         int32   (160000)
//   4: edge_type      int32   (160000)
//   5: edge_weights   float32 (160000)
//   6: blocks         float32 (17*32*4*4)
// Output: float32 (10000*128)
// ---------------------------------------------------------------------------
extern "C" void kernel_launch(void* const* d_in, const int* in_sizes, int n_in,
                              void* d_out, int out_size)
{
    const float* x      = (const float*)d_in[0];
    const int*   mask   = (const int*)d_in[1];
    const int*   src    = (const int*)d_in[2];
    const int*   tgt    = (const int*)d_in[3];
    const int*   et     = (const int*)d_in[4];
    const float* ew     = (const float*)d_in[5];
    const float* blocks = (const float*)d_in[6];
    float*       out    = (float*)d_out;

    const int n_nodes = in_sizes[1];
    const int n_edges = in_sizes[2];

    // 1) Self-loop + out init
    self_kernel<<<592, 256>>>(x, mask, blocks, out, n_nodes);

    // 2) Relation-specialized edge messages (serial inner loop, big grid)
    dim3 grid(EDGE_G, NREL);
    edge_kernel<<<grid, EDGE_THREADS>>>(x, src, tgt, et, ew, blocks, out, n_edges);
}